// round 12
// baseline (speedup 1.0000x reference)
#include <cuda_runtime.h>

#define IMG_H 512
#define IMG_W 512
#define NIMG  16
#define TW    32
#define TH    32
#define RH    42            // TH + 10 halo rows of hblur
#define HSTR2 33            // hblur stride in ulonglong2 (16B) units
#define NPIX  (NIMG * IMG_H * IMG_W)
#define NBLK  (NIMG * (IMG_H / TH) * (IMG_W / TW))   // 4096
#define NT    512

typedef unsigned long long u64;

__device__ float        g_part[NBLK];
__device__ unsigned int g_count;     // zero-init at load; reset by last block

// ---- packed f32x2 helpers (sm_100+; ptxas never emits these from C++) ----
__device__ __forceinline__ u64 pk(float lo, float hi) {
    u64 r; asm("mov.b64 %0, {%1, %2};" : "=l"(r) : "f"(lo), "f"(hi)); return r;
}
__device__ __forceinline__ void upk(float& lo, float& hi, u64 v) {
    asm("mov.b64 {%0, %1}, %2;" : "=f"(lo), "=f"(hi) : "l"(v));
}
__device__ __forceinline__ u64 fma2(u64 a, u64 b, u64 c) {
    u64 d; asm("fma.rn.f32x2 %0, %1, %2, %3;" : "=l"(d) : "l"(a), "l"(b), "l"(c)); return d;
}

__global__ void __launch_bounds__(NT, 2) ssim_kernel(
    const float* __restrict__ fused,
    const float* __restrict__ imga,
    const float* __restrict__ imgb,
    float* __restrict__ out)
{
    // Channel-interleaved hblur:
    //   hbA[y][x] = ( pk(muF,muA), pk(muB,eF2) )
    //   hbB[y][x] = ( pk(eA2,eB2), pk(eFA,eFB) )
    extern __shared__ ulonglong2 smem2[];
    ulonglong2* hbA = smem2;                   // [RH][HSTR2]
    ulonglong2* hbB = hbA + RH * HSTR2;        // [RH][HSTR2]

    constexpr float GW[11] = {
        0.00102838f, 0.00759876f, 0.03600077f, 0.10936069f, 0.21300553f,
        0.26601172f,
        0.21300553f, 0.10936069f, 0.03600077f, 0.00759876f, 0.00102838f};
    const float c1 = 0.0001f;
    const float c2 = 0.0009f;

    const int tid = threadIdx.x;
    const int bx  = blockIdx.x;
    const int gy0 = blockIdx.y * TH - 5;
    const size_t base = (size_t)blockIdx.z * (IMG_H * IMG_W);
    const float* fP = fused + base;
    const float* aP = imga + base;
    const float* bP = imgb + base;
    const bool edge_x = (bx == 0) | (bx == (IMG_W / TW) - 1);

    // ---- Stage 1: horizontal blur straight from gmem, 4 outputs/task ----
    // 336 tasks on 512 threads: exactly one task per thread, no straggler.
    // Scalar FFMA-imm accumulation (weights ride as instruction immediates).
    if (tid < RH * 8) {
        const int y  = tid >> 3;
        const int x0 = (tid & 7) * 4;
        const int gy = gy0 + y;

        float acc[4][8];
#pragma unroll
        for (int j = 0; j < 4; j++)
#pragma unroll
            for (int c = 0; c < 8; c++) acc[j][c] = 0.f;

        if (gy >= 0 && gy < IMG_H) {
            if (!edge_x) {
                const int gxa = bx * TW + x0 - 8;       // multiple of 4, >=24
                const float4* f4 = (const float4*)(fP + gy * IMG_W + gxa);
                const float4* a4 = (const float4*)(aP + gy * IMG_W + gxa);
                const float4* b4 = (const float4*)(bP + gy * IMG_W + gxa);
#pragma unroll
                for (int q = 0; q < 5; q++) {
                    float4 fv = f4[q], av = a4[q], bv = b4[q];
                    float fs[4] = {fv.x, fv.y, fv.z, fv.w};
                    float as[4] = {av.x, av.y, av.z, av.w};
                    float bs[4] = {bv.x, bv.y, bv.z, bv.w};
#pragma unroll
                    for (int m = 0; m < 4; m++) {
                        int k = q * 4 + m - 3;          // window px 0..13
                        if (k < 0 || k >= 14) continue;
                        float f = fmaf(fs[m], 0.5f, 0.5f);
                        float a = fmaf(as[m], 0.5f, 0.5f);
                        float b = fmaf(bs[m], 0.5f, 0.5f);
                        float v[8] = {f, a, b, f * f, a * a, b * b,
                                      f * a, f * b};
#pragma unroll
                        for (int j = 0; j < 4; j++) {
                            int tt = k - j;             // compile-time
                            if (tt >= 0 && tt < 11) {
#pragma unroll
                                for (int c = 0; c < 8; c++)
                                    acc[j][c] = fmaf(v[c], GW[tt], acc[j][c]);
                            }
                        }
                    }
                }
            } else {
                const int gxw = bx * TW + x0 - 5;
                const float* frow = fP + gy * IMG_W;
                const float* arow = aP + gy * IMG_W;
                const float* brow = bP + gy * IMG_W;
#pragma unroll
                for (int k = 0; k < 14; k++) {
                    int gx = gxw + k;
                    float f = 0.f, a = 0.f, b = 0.f;
                    if (gx >= 0 && gx < IMG_W) {
                        f = fmaf(frow[gx], 0.5f, 0.5f);
                        a = fmaf(arow[gx], 0.5f, 0.5f);
                        b = fmaf(brow[gx], 0.5f, 0.5f);
                    }
                    float v[8] = {f, a, b, f * f, a * a, b * b, f * a, f * b};
#pragma unroll
                    for (int j = 0; j < 4; j++) {
                        int tt = k - j;
                        if (tt >= 0 && tt < 11) {
#pragma unroll
                            for (int c = 0; c < 8; c++)
                                acc[j][c] = fmaf(v[c], GW[tt], acc[j][c]);
                        }
                    }
                }
            }
        }

        ulonglong2* pA = hbA + y * HSTR2 + x0;
        ulonglong2* pB = hbB + y * HSTR2 + x0;
#pragma unroll
        for (int j = 0; j < 4; j++) {
            pA[j] = make_ulonglong2(pk(acc[j][0], acc[j][1]),
                                    pk(acc[j][2], acc[j][3]));
            pB[j] = make_ulonglong2(pk(acc[j][4], acc[j][5]),
                                    pk(acc[j][6], acc[j][7]));
        }
    }
    __syncthreads();

    // ---- Stage 2: vertical blur (2 outputs/thread, 16 warps) + SSIM ----
    float lsum = 0.f;
    {
        const int x  = tid & 31;
        const int yb = (tid >> 5) * 2;      // 16 warps x 2 rows = 32 rows

        u64 acc[2][4];
#pragma unroll
        for (int j = 0; j < 2; j++)
#pragma unroll
            for (int c = 0; c < 4; c++) acc[j][c] = 0ull;

#pragma unroll
        for (int r = 0; r < 12; r++) {
            ulonglong2 qA = hbA[(yb + r) * HSTR2 + x];
            ulonglong2 qB = hbB[(yb + r) * HSTR2 + x];
#pragma unroll
            for (int j = 0; j < 2; j++) {
                int tt = r - j;
                if (tt >= 0 && tt < 11) {
                    u64 w = pk(GW[tt], GW[tt]);
                    acc[j][0] = fma2(qA.x, w, acc[j][0]);
                    acc[j][1] = fma2(qA.y, w, acc[j][1]);
                    acc[j][2] = fma2(qB.x, w, acc[j][2]);
                    acc[j][3] = fma2(qB.y, w, acc[j][3]);
                }
            }
        }

#pragma unroll
        for (int j = 0; j < 2; j++) {
            float muF, muA, muB, eF2, eA2, eB2, eFA, eFB;
            upk(muF, muA, acc[j][0]);
            upk(muB, eF2, acc[j][1]);
            upk(eA2, eB2, acc[j][2]);
            upk(eFA, eFB, acc[j][3]);
            float muF2 = muF * muF;
            float sF2  = eF2 - muF2;
            float muA2 = muA * muA;
            float m12a = muF * muA;
            float sA2  = eA2 - muA2;
            float s12a = eFA - m12a;
            float na   = (2.f * m12a + c1) * (2.f * s12a + c2);
            float da   = (muF2 + muA2 + c1) * (sF2 + sA2 + c2);
            float muB2 = muB * muB;
            float m12b = muF * muB;
            float sB2  = eB2 - muB2;
            float s12b = eFB - m12b;
            float nb   = (2.f * m12b + c1) * (2.f * s12b + c2);
            float db   = (muF2 + muB2 + c1) * (sF2 + sB2 + c2);
            float num = fmaf(na, db, nb * da);
            lsum += __fdividef(num, da * db);
        }
    }

    // ---- Block reduction -> deterministic per-block partial ----
#pragma unroll
    for (int o = 16; o > 0; o >>= 1)
        lsum += __shfl_down_sync(0xffffffffu, lsum, o);

    __shared__ float wsum[16];
    __shared__ bool  is_last;
    if ((tid & 31) == 0) wsum[tid >> 5] = lsum;
    __syncthreads();
    if (tid == 0) {
        float v = 0.f;
#pragma unroll
        for (int w = 0; w < 16; w++) v += wsum[w];
        int bi = ((int)blockIdx.z * gridDim.y + blockIdx.y) * gridDim.x
                 + blockIdx.x;
        g_part[bi] = v;
        __threadfence();
        unsigned prev = atomicAdd(&g_count, 1u);
        is_last = (prev == NBLK - 1);
    }
    __syncthreads();

    if (is_last) {
        double s = 0.0;
        for (int i = tid; i < NBLK; i += NT) s += (double)g_part[i];
#pragma unroll
        for (int o = 16; o > 0; o >>= 1)
            s += __shfl_down_sync(0xffffffffu, s, o);
        __shared__ double dsum[16];
        if ((tid & 31) == 0) dsum[tid >> 5] = s;
        __syncthreads();
        if (tid == 0) {
            double tot = 0.0;
#pragma unroll
            for (int w = 0; w < 16; w++) tot += dsum[w];
            out[0] = (float)(1.0 - tot / (2.0 * (double)NPIX));
            g_count = 0;      // reset for next graph replay
        }
    }
}

extern "C" void kernel_launch(void* const* d_in, const int* in_sizes, int n_in,
                              void* d_out, int out_size)
{
    (void)in_sizes; (void)n_in; (void)out_size;
    const float* fused = (const float*)d_in[0];
    const float* imga  = (const float*)d_in[1];
    const float* imgb  = (const float*)d_in[2];

    const size_t smem_bytes = (size_t)(2 * RH * HSTR2) * sizeof(ulonglong2); // 44.4 KB
    cudaFuncSetAttribute(ssim_kernel,
                         cudaFuncAttributeMaxDynamicSharedMemorySize,
                         (int)smem_bytes);

    dim3 grid(IMG_W / TW, IMG_H / TH, NIMG);
    ssim_kernel<<<grid, NT, smem_bytes>>>(fused, imga, imgb, (float*)d_out);
}

// round 13
// speedup vs baseline: 1.3315x; 1.3315x over previous
#include <cuda_runtime.h>

#define IMG_H 512
#define IMG_W 512
#define NIMG  16
#define TW    32
#define TH    32
#define RH    42            // TH + 10 halo rows of hblur
#define HSTR  34            // hblur u64 stride (even -> 16B-aligned px pairs)
#define NPIX  (NIMG * IMG_H * IMG_W)
#define NBLK  (NIMG * (IMG_H / TH) * (IMG_W / TW))   // 4096
#define NT    352           // 11 warps: 336 stage-1 tasks in ONE pass

typedef unsigned long long u64;

__device__ float        g_part[NBLK];
__device__ unsigned int g_count;     // zero-init at load; reset by last block

// ---- packed f32x2 helpers (sm_100+; ptxas never emits these from C++) ----
__device__ __forceinline__ u64 pk(float lo, float hi) {
    u64 r; asm("mov.b64 %0, {%1, %2};" : "=l"(r) : "f"(lo), "f"(hi)); return r;
}
__device__ __forceinline__ void upk(float& lo, float& hi, u64 v) {
    asm("mov.b64 {%0, %1}, %2;" : "=f"(lo), "=f"(hi) : "l"(v));
}
__device__ __forceinline__ u64 fma2(u64 a, u64 b, u64 c) {
    u64 d; asm("fma.rn.f32x2 %0, %1, %2, %3;" : "=l"(d) : "l"(a), "l"(b), "l"(c)); return d;
}

__global__ void __launch_bounds__(NT, 3) ssim_kernel(
    const float* __restrict__ fused,
    const float* __restrict__ imga,
    const float* __restrict__ imgb,
    float* __restrict__ out)
{
    extern __shared__ u64 smem[];
    u64* hb0 = smem;                       // [RH][HSTR] packed (muF, muA)
    u64* hb1 = hb0 + RH * HSTR;            // (muB, eF2)
    u64* hb2 = hb1 + RH * HSTR;            // (eA2, eB2)
    u64* hb3 = hb2 + RH * HSTR;            // (eFA, eFB)

    constexpr float GW[11] = {
        0.00102838f, 0.00759876f, 0.03600077f, 0.10936069f, 0.21300553f,
        0.26601172f,
        0.21300553f, 0.10936069f, 0.03600077f, 0.00759876f, 0.00102838f};
    const float c1 = 0.0001f;
    const float c2 = 0.0009f;

    const int tid = threadIdx.x;
    const int bx  = blockIdx.x;
    const int gy0 = blockIdx.y * TH - 5;
    const size_t base = (size_t)blockIdx.z * (IMG_H * IMG_W);
    const float* fP = fused + base;
    const float* aP = imga + base;
    const float* bP = imgb + base;
    const bool edge_x = (bx == 0) | (bx == (IMG_W / TW) - 1);

    // ---- Stage 1: horizontal blur straight from gmem, 4 outputs/task ----
    // 336 tasks on 352 threads: SINGLE pass, no straggler second task.
    // Scalar FFMA-imm accumulation (weights ride as instruction immediates).
    if (tid < RH * 8) {
        const int y  = tid >> 3;
        const int x0 = (tid & 7) * 4;
        const int gy = gy0 + y;

        float acc[4][8];
#pragma unroll
        for (int j = 0; j < 4; j++)
#pragma unroll
            for (int c = 0; c < 8; c++) acc[j][c] = 0.f;

        if (gy >= 0 && gy < IMG_H) {
            if (!edge_x) {
                const int gxa = bx * TW + x0 - 8;       // multiple of 4, >=24
                const float4* f4 = (const float4*)(fP + gy * IMG_W + gxa);
                const float4* a4 = (const float4*)(aP + gy * IMG_W + gxa);
                const float4* b4 = (const float4*)(bP + gy * IMG_W + gxa);
#pragma unroll
                for (int q = 0; q < 5; q++) {
                    float4 fv = f4[q], av = a4[q], bv = b4[q];
                    float fs[4] = {fv.x, fv.y, fv.z, fv.w};
                    float as[4] = {av.x, av.y, av.z, av.w};
                    float bs[4] = {bv.x, bv.y, bv.z, bv.w};
#pragma unroll
                    for (int m = 0; m < 4; m++) {
                        int k = q * 4 + m - 3;          // window px 0..13
                        if (k < 0 || k >= 14) continue;
                        float f = fmaf(fs[m], 0.5f, 0.5f);
                        float a = fmaf(as[m], 0.5f, 0.5f);
                        float b = fmaf(bs[m], 0.5f, 0.5f);
                        float v[8] = {f, a, b, f * f, a * a, b * b,
                                      f * a, f * b};
#pragma unroll
                        for (int j = 0; j < 4; j++) {
                            int tt = k - j;             // compile-time
                            if (tt >= 0 && tt < 11) {
#pragma unroll
                                for (int c = 0; c < 8; c++)
                                    acc[j][c] = fmaf(v[c], GW[tt], acc[j][c]);
                            }
                        }
                    }
                }
            } else {
                const int gxw = bx * TW + x0 - 5;
                const float* frow = fP + gy * IMG_W;
                const float* arow = aP + gy * IMG_W;
                const float* brow = bP + gy * IMG_W;
#pragma unroll
                for (int k = 0; k < 14; k++) {
                    int gx = gxw + k;
                    float f = 0.f, a = 0.f, b = 0.f;
                    if (gx >= 0 && gx < IMG_W) {
                        f = fmaf(frow[gx], 0.5f, 0.5f);
                        a = fmaf(arow[gx], 0.5f, 0.5f);
                        b = fmaf(brow[gx], 0.5f, 0.5f);
                    }
                    float v[8] = {f, a, b, f * f, a * a, b * b, f * a, f * b};
#pragma unroll
                    for (int j = 0; j < 4; j++) {
                        int tt = k - j;
                        if (tt >= 0 && tt < 11) {
#pragma unroll
                            for (int c = 0; c < 8; c++)
                                acc[j][c] = fmaf(v[c], GW[tt], acc[j][c]);
                        }
                    }
                }
            }
        }

        const int o = y * HSTR + x0;
#pragma unroll
        for (int j = 0; j < 4; j++) {
            hb0[o + j] = pk(acc[j][0], acc[j][1]);
            hb1[o + j] = pk(acc[j][2], acc[j][3]);
            hb2[o + j] = pk(acc[j][4], acc[j][5]);
            hb3[o + j] = pk(acc[j][6], acc[j][7]);
        }
    }
    __syncthreads();

    // ---- Stage 2: vertical blur + SSIM.  11 warps x 3 rows (warp 10: 2) ----
    float lsum = 0.f;
    {
        const int x    = tid & 31;
        const int warp = tid >> 5;
        const int yb   = warp * 3;
        const int nrows = (warp == 10) ? 2 : 3;

        u64 acc[3][4];
#pragma unroll
        for (int j = 0; j < 3; j++)
#pragma unroll
            for (int c = 0; c < 4; c++) acc[j][c] = 0ull;

#pragma unroll
        for (int r = 0; r < 13; r++) {
            if (r >= nrows + 10) break;     // warp-uniform bound (12 or 13)
            int o = (yb + r) * HSTR + x;
            u64 q0 = hb0[o], q1 = hb1[o], q2 = hb2[o], q3 = hb3[o];
#pragma unroll
            for (int j = 0; j < 3; j++) {
                int tt = r - j;
                if (tt >= 0 && tt < 11) {
                    u64 w = pk(GW[tt], GW[tt]);
                    acc[j][0] = fma2(q0, w, acc[j][0]);
                    acc[j][1] = fma2(q1, w, acc[j][1]);
                    acc[j][2] = fma2(q2, w, acc[j][2]);
                    acc[j][3] = fma2(q3, w, acc[j][3]);
                }
            }
        }

#pragma unroll
        for (int j = 0; j < 3; j++) {
            if (j >= nrows) break;          // warp-uniform
            float muF, muA, muB, eF2, eA2, eB2, eFA, eFB;
            upk(muF, muA, acc[j][0]);
            upk(muB, eF2, acc[j][1]);
            upk(eA2, eB2, acc[j][2]);
            upk(eFA, eFB, acc[j][3]);
            float muF2 = muF * muF;
            float sF2  = eF2 - muF2;
            float muA2 = muA * muA;
            float m12a = muF * muA;
            float sA2  = eA2 - muA2;
            float s12a = eFA - m12a;
            float na   = (2.f * m12a + c1) * (2.f * s12a + c2);
            float da   = (muF2 + muA2 + c1) * (sF2 + sA2 + c2);
            float muB2 = muB * muB;
            float m12b = muF * muB;
            float sB2  = eB2 - muB2;
            float s12b = eFB - m12b;
            float nb   = (2.f * m12b + c1) * (2.f * s12b + c2);
            float db   = (muF2 + muB2 + c1) * (sF2 + sB2 + c2);
            float num = fmaf(na, db, nb * da);
            lsum += __fdividef(num, da * db);
        }
    }

    // ---- Block reduction -> deterministic per-block partial ----
#pragma unroll
    for (int o = 16; o > 0; o >>= 1)
        lsum += __shfl_down_sync(0xffffffffu, lsum, o);

    __shared__ float wsum[11];
    __shared__ bool  is_last;
    if ((tid & 31) == 0) wsum[tid >> 5] = lsum;
    __syncthreads();
    if (tid == 0) {
        float v = 0.f;
#pragma unroll
        for (int w = 0; w < 11; w++) v += wsum[w];
        int bi = ((int)blockIdx.z * gridDim.y + blockIdx.y) * gridDim.x
                 + blockIdx.x;
        g_part[bi] = v;
        __threadfence();
        unsigned prev = atomicAdd(&g_count, 1u);
        is_last = (prev == NBLK - 1);
    }
    __syncthreads();

    if (is_last) {
        double s = 0.0;
        for (int i = tid; i < NBLK; i += NT) s += (double)g_part[i];
#pragma unroll
        for (int o = 16; o > 0; o >>= 1)
            s += __shfl_down_sync(0xffffffffu, s, o);
        __shared__ double dsum[11];
        if ((tid & 31) == 0) dsum[tid >> 5] = s;
        __syncthreads();
        if (tid == 0) {
            double tot = 0.0;
#pragma unroll
            for (int w = 0; w < 11; w++) tot += dsum[w];
            out[0] = (float)(1.0 - tot / (2.0 * (double)NPIX));
            g_count = 0;      // reset for next graph replay
        }
    }
}

extern "C" void kernel_launch(void* const* d_in, const int* in_sizes, int n_in,
                              void* d_out, int out_size)
{
    (void)in_sizes; (void)n_in; (void)out_size;
    const float* fused = (const float*)d_in[0];
    const float* imga  = (const float*)d_in[1];
    const float* imgb  = (const float*)d_in[2];

    const size_t smem_bytes = (size_t)(4 * RH * HSTR) * sizeof(u64); // 44.6 KB
    cudaFuncSetAttribute(ssim_kernel,
                         cudaFuncAttributeMaxDynamicSharedMemorySize,
                         (int)smem_bytes);

    dim3 grid(IMG_W / TW, IMG_H / TH, NIMG);
    ssim_kernel<<<grid, NT, smem_bytes>>>(fused, imga, imgb, (float*)d_out);
}